// round 11
// baseline (speedup 1.0000x reference)
#include <cuda_runtime.h>
#include <math.h>

#define BB 1024
#define DIMC 384
#define NN 49
#define HEADS 8
#define KD 32
#define DV 128
#define DHC 1024
#define CQKV 1536

// k-permutation within groups of 8: puts (k, k+4) fragment pairs adjacent for LDS.64.
#define KPERM(k) (((k) & ~7) | (((k) & 3) << 1) | ((((k) >> 2)) & 1))

// attn_out smem layout (floats)
#define QK_STRIDE 36
#define OFF_K   14112            // 8*49*36
#define OFF_R2  28224            // q,k region size
#define OFF_ABS 47432            // 28224 + 19208
#define OFF_T1W 47824
#define OFF_T1B 47888
#define OFF_T2W 47896
#define OFF_T2B 47960
#define SMEM_FLOATS 47968        // 191872 bytes
#define VT_STRIDE 132

// ---------------- scratch (static device allocations) ----------------
__device__ unsigned g_w[CQKV * DIMC];           // fused qkv weights, tf32 bits, k-permuted
__device__ float g_bias[CQKV];
__device__ unsigned g_pw[DIMC * DHC];           // fused proj weights, tf32 bits, k-permuted
__device__ float g_pb[DIMC];
__device__ float g_vlw[DHC * 9];                // fused depthwise weights
__device__ float g_vlb[DHC];
__device__ unsigned g_xt[(size_t)BB * NN * DIMC];   // x transposed [b][n][c], tf32 bits
__device__ float g_qkv[(size_t)BB * CQKV * NN];     // 308 MB
__device__ unsigned g_ht[(size_t)BB * NN * DHC];    // hidden transposed [b][n][d], tf32

// ---------------- tf32 mma helpers ----------------
__device__ __forceinline__ unsigned cvt_tf32(float f) {
    unsigned r;
    asm("cvt.rna.tf32.f32 %0, %1;" : "=r"(r) : "f"(f));
    return r;
}
__device__ __forceinline__ void mma8(float* d, unsigned a0, unsigned a1, unsigned a2,
                                     unsigned a3, unsigned b0, unsigned b1) {
    asm("mma.sync.aligned.m16n8k8.row.col.f32.tf32.tf32.f32 "
        "{%0,%1,%2,%3},{%4,%5,%6,%7},{%8,%9},{%0,%1,%2,%3};"
        : "+f"(d[0]), "+f"(d[1]), "+f"(d[2]), "+f"(d[3])
        : "r"(a0), "r"(a1), "r"(a2), "r"(a3), "r"(b0), "r"(b1));
}

// ---------------- prep: fold BN affines / scales into weights ----------------
__global__ void prep_kernel(const float* __restrict__ qw, const float* __restrict__ qb,
                            const float* __restrict__ qs, const float* __restrict__ qo,
                            const float* __restrict__ kw, const float* __restrict__ kb,
                            const float* __restrict__ ks, const float* __restrict__ ko,
                            const float* __restrict__ vw, const float* __restrict__ vb,
                            const float* __restrict__ vs, const float* __restrict__ vo,
                            const float* __restrict__ vlw, const float* __restrict__ vlb,
                            const float* __restrict__ vls, const float* __restrict__ vlo,
                            const float* __restrict__ pw, const float* __restrict__ pb,
                            const float* __restrict__ ps, const float* __restrict__ po) {
    int i = blockIdx.x * blockDim.x + threadIdx.x;
    const float SCALE = 0.17677669529663687f;  // 32^-0.5, folded into q
    if (i < CQKV * DIMC) {
        int o = i / DIMC, c = i - o * DIMC;
        float v;
        if (o < 256)       v = qw[o * DIMC + c] * qs[o] * SCALE;
        else if (o < 512)  { int oo = o - 256; v = kw[oo * DIMC + c] * ks[oo]; }
        else               { int oo = o - 512; v = vw[oo * DIMC + c] * vs[oo]; }
        g_w[o * DIMC + KPERM(c)] = cvt_tf32(v);
    }
    if (i < CQKV) {
        float v;
        if (i < 256)       v = (qb[i] * qs[i] + qo[i]) * SCALE;
        else if (i < 512)  { int oo = i - 256; v = kb[oo] * ks[oo] + ko[oo]; }
        else               { int oo = i - 512; v = vb[oo] * vs[oo] + vo[oo]; }
        g_bias[i] = v;
    }
    if (i < DIMC * DHC) {
        int o = i / DHC, c = i - o * DHC;
        g_pw[o * DHC + KPERM(c)] = cvt_tf32(pw[i] * ps[o]);
    }
    if (i < DIMC)  g_pb[i] = pb[i] * ps[i] + po[i];
    if (i < DHC * 9) { int c = i / 9; g_vlw[i] = vlw[i] * vls[c]; }
    if (i < DHC)   g_vlb[i] = vlb[i] * vls[i] + vlo[i];
}

// ---------------- transpose x: [b][c][n] fp32 -> [b][n][c] tf32 bits ----------------
__global__ __launch_bounds__(256) void xt_kernel(const float* __restrict__ x) {
    extern __shared__ float sx[];  // 384*49 floats
    int b = blockIdx.x;
    int tid = threadIdx.x;
    const float* xb = x + (size_t)b * DIMC * NN;
    for (int i = tid; i < DIMC * NN; i += 256) sx[i] = xb[i];
    __syncthreads();
    unsigned* ob = g_xt + (size_t)b * NN * DIMC;
    for (int i = tid; i < NN * DIMC; i += 256) {
        int n = i / DIMC, c = i - n * DIMC;
        ob[i] = cvt_tf32(sx[c * NN + n]);
    }
}

// ---------------- tensor-core GEMM (unchanged from R10) ----------------
__global__ __launch_bounds__(128) void gemm_tc(const unsigned* __restrict__ W,
                                               const float* __restrict__ bias,
                                               const unsigned* __restrict__ Xt,
                                               float* __restrict__ Y, int O, int K) {
    __shared__ unsigned ws[128][40];   // [o][k-permuted], stride 40
    __shared__ unsigned xs[56][40];    // [n][k natural], rows 49..55 zero
    __shared__ float bs[128];
    int b = blockIdx.y;
    int obase = blockIdx.x * 128;
    const unsigned* Xb = Xt + (size_t)b * NN * K;
    float* Yb = Y + (size_t)b * O * NN;
    int tid = threadIdx.x;
    int warp = tid >> 5, lane = tid & 31;
    int g = lane >> 2, t = lane & 3;
    int m0 = warp * 32;

    float acc[2][7][4];
#pragma unroll
    for (int mt = 0; mt < 2; mt++)
#pragma unroll
        for (int nt = 0; nt < 7; nt++)
#pragma unroll
            for (int x = 0; x < 4; x++) acc[mt][nt][x] = 0.f;

    bs[tid] = bias[obase + tid];
    for (int i = tid; i < 7 * 40; i += 128) xs[49 + i / 40][i % 40] = 0u;

    for (int c0 = 0; c0 < K; c0 += 32) {
        __syncthreads();
        for (int i = tid; i < 1024; i += 128) {
            int o = i >> 3, c4 = (i & 7) << 2;
            *(uint4*)&ws[o][c4] = *(const uint4*)&W[(size_t)(obase + o) * K + c0 + c4];
        }
        for (int i = tid; i < 392; i += 128) {
            int n = i >> 3, c4 = (i & 7) << 2;
            *(uint4*)&xs[n][c4] = *(const uint4*)&Xb[(size_t)n * K + c0 + c4];
        }
        __syncthreads();
#pragma unroll
        for (int kk8 = 0; kk8 < 4; kk8++) {
            int kc = kk8 * 8 + 2 * t;
            int kn = kk8 * 8 + t;
            uint2 p0 = *(const uint2*)&ws[m0 + g][kc];
            uint2 p1 = *(const uint2*)&ws[m0 + 8 + g][kc];
            uint2 p2 = *(const uint2*)&ws[m0 + 16 + g][kc];
            uint2 p3 = *(const uint2*)&ws[m0 + 24 + g][kc];
#pragma unroll
            for (int nt = 0; nt < 7; nt++) {
                unsigned b0 = xs[nt * 8 + g][kn];
                unsigned b1 = xs[nt * 8 + g][kn + 4];
                mma8(acc[0][nt], p0.x, p1.x, p0.y, p1.y, b0, b1);
                mma8(acc[1][nt], p2.x, p3.x, p2.y, p3.y, b0, b1);
            }
        }
    }

#pragma unroll
    for (int mt = 0; mt < 2; mt++) {
        int r0 = m0 + mt * 16 + g;
        float bv0 = bs[r0], bv1 = bs[r0 + 8];
        size_t base0 = (size_t)(obase + r0) * NN;
        size_t base1 = (size_t)(obase + r0 + 8) * NN;
#pragma unroll
        for (int nt = 0; nt < 7; nt++) {
            int col = nt * 8 + 2 * t;
            if (col < NN) {
                Yb[base0 + col] = acc[mt][nt][0] + bv0;
                Yb[base1 + col] = acc[mt][nt][2] + bv1;
            }
            if (col + 1 < NN) {
                Yb[base0 + col + 1] = acc[mt][nt][1] + bv0;
                Yb[base1 + col + 1] = acc[mt][nt][3] + bv1;
            }
        }
    }
}

// ---------------- fused attention core + attn@V + depthwise + GELU ----------------
// Vectorized SMEM layouts:
//   r1 phase A: q[h][n][36] (kd 0..31), k at OFF_K + [h][m][36]
//   r2 scores: [n][m][8] head-interleaved
//   r1 phase B (th1 out / softmax): [n][m][8]
//   r2 phase B (th2 out): attn transposed [i][m][n] (i*2401 + m*49 + n)
//   r1 phase C (per head): v transposed [m][132] (d 0..127)
__global__ __launch_bounds__(256) void attn_out_kernel(const float* __restrict__ ab,
                                                       const float* __restrict__ th1w_g,
                                                       const float* __restrict__ th1b_g,
                                                       const float* __restrict__ th2w_g,
                                                       const float* __restrict__ th2b_g) {
    extern __shared__ float sm[];
    float* r1 = sm;
    float* r2 = sm + OFF_R2;
    float* abs_ = sm + OFF_ABS;
    float* t1w = sm + OFF_T1W;
    float* t1b = sm + OFF_T1B;
    float* t2w = sm + OFF_T2W;
    float* t2b = sm + OFF_T2B;
    int b = blockIdx.x;
    int tid = threadIdx.x;
    const float* qkbase = g_qkv + (size_t)b * CQKV * NN;  // channels 0..511 = q,k

    // fill q,k transposed: [h][n][kd] stride 36
    for (int i = tid; i < 512 * NN; i += 256) {
        int c = i / NN, n = i - c * NN;
        float v = qkbase[i];
        int h = (c & 255) >> 5, kd = c & 31;
        int dst = (c < 256 ? 0 : OFF_K) + (h * NN + n) * QK_STRIDE + kd;
        r1[dst] = v;
    }
    for (int i = tid; i < 392; i += 256) abs_[i] = ab[i];
    if (tid < 64) { t1w[tid] = th1w_g[tid]; t2w[tid] = th2w_g[tid]; }
    if (tid < 8)  { t1b[tid] = th1b_g[tid]; t2b[tid] = th2b_g[tid]; }
    __syncthreads();

    // scores: r2[n][m][h] = q·k + rel-pos bias (vector k-row loads)
    for (int p = tid; p < HEADS * NN; p += 256) {
        int h = p / NN, n = p - h * NN;
        float qv[KD];
        const float4* qrow = (const float4*)&r1[(h * NN + n) * QK_STRIDE];
#pragma unroll
        for (int q4 = 0; q4 < 8; q4++) {
            float4 v = qrow[q4];
            qv[4 * q4] = v.x; qv[4 * q4 + 1] = v.y; qv[4 * q4 + 2] = v.z; qv[4 * q4 + 3] = v.w;
        }
        int ny = n / 7, nx = n - ny * 7;
        const float* kbase = r1 + OFF_K + h * NN * QK_STRIDE;
        const float* abh = abs_ + h * NN;
        for (int m = 0; m < NN; m++) {
            const float4* krow = (const float4*)&kbase[m * QK_STRIDE];
            float s = 0.f;
#pragma unroll
            for (int q4 = 0; q4 < 8; q4++) {
                float4 kv = krow[q4];
                s += qv[4 * q4] * kv.x + qv[4 * q4 + 1] * kv.y
                   + qv[4 * q4 + 2] * kv.z + qv[4 * q4 + 3] * kv.w;
            }
            int my = m / 7, mx = m - my * 7;
            int ridx = abs(ny - my) * 7 + abs(nx - mx);
            r2[(n * NN + m) * 8 + h] = s + abh[ridx];
        }
    }
    __syncthreads();

    // th1 head mix: r2[n][m][j] -> r1[n][m][i] (q/k dead)
    for (int p = tid; p < HEADS * NN; p += 256) {
        int i = p / NN, n = p - i * NN;
        float w[8];
#pragma unroll
        for (int j = 0; j < 8; j++) w[j] = t1w[i * 8 + j];
        float bi = t1b[i];
        for (int m = 0; m < NN; m++) {
            const float4* grp = (const float4*)&r2[(n * NN + m) * 8];
            float4 v0 = grp[0], v1 = grp[1];
            float s = bi + w[0] * v0.x + w[1] * v0.y + w[2] * v0.z + w[3] * v0.w
                         + w[4] * v1.x + w[5] * v1.y + w[6] * v1.z + w[7] * v1.w;
            r1[(n * NN + m) * 8 + i] = s;
        }
    }
    __syncthreads();

    // softmax over m for each (i,n), stride-8 rows in r1
    for (int p = tid; p < HEADS * NN; p += 256) {
        int i = p / NN, n = p - i * NN;
        float* row = r1 + n * NN * 8 + i;
        float mx = row[0];
        for (int m = 1; m < NN; m++) mx = fmaxf(mx, row[m * 8]);
        float sum = 0.f;
        for (int m = 0; m < NN; m++) {
            float e = __expf(row[m * 8] - mx);
            row[m * 8] = e;
            sum += e;
        }
        float inv = 1.f / sum;
        for (int m = 0; m < NN; m++) row[m * 8] *= inv;
    }
    __syncthreads();

    // th2 head mix: r1[n][m][j] -> r2 attn transposed [i][m][n] (scores dead)
    for (int p = tid; p < HEADS * NN; p += 256) {
        int i = p / NN, n = p - i * NN;
        float w[8];
#pragma unroll
        for (int j = 0; j < 8; j++) w[j] = t2w[i * 8 + j];
        float bi = t2b[i];
        for (int m = 0; m < NN; m++) {
            const float4* grp = (const float4*)&r1[(n * NN + m) * 8];
            float4 v0 = grp[0], v1 = grp[1];
            float s = bi + w[0] * v0.x + w[1] * v0.y + w[2] * v0.z + w[3] * v0.w
                         + w[4] * v1.x + w[5] * v1.y + w[6] * v1.z + w[7] * v1.w;
            r2[i * (NN * NN) + m * NN + n] = s;
        }
    }

    // per-head: attn@V + depthwise conv + GELU; V transposed [m][d] in r1
    int dg = tid / 7, y = tid - dg * 7;   // dg 0..36 (use <32), y 0..6
    int d0 = dg * 4;
    for (int h = 0; h < HEADS; h++) {
        __syncthreads();  // prev head compute done (and th2 done on first iter)
        const float* vp = g_qkv + (size_t)b * CQKV * NN + (size_t)(512 + h * DV) * NN;
        // fill vt[m][d]: read [d][n] coalesced, write transposed
        for (int i = tid; i < DV * NN; i += 256) {
            int d = i / NN, n = i - d * NN;
            r1[n * VT_STRIDE + d] = vp[i];
        }
        __syncthreads();
        if (dg < 32) {
            const float* at_ = r2 + (size_t)h * NN * NN;  // [m*49 + n]
            float acc[7][4];
#pragma unroll
            for (int x = 0; x < 7; x++)
#pragma unroll
                for (int j = 0; j < 4; j++) acc[x][j] = 0.f;

            for (int m = 0; m < NN; m++) {
                float a[7];
                const float* arow = at_ + m * NN + y * 7;
#pragma unroll
                for (int x = 0; x < 7; x++) a[x] = arow[x];
                float4 v = *(const float4*)&r1[m * VT_STRIDE + d0];
#pragma unroll
                for (int x = 0; x < 7; x++) {
                    acc[x][0] += a[x] * v.x;
                    acc[x][1] += a[x] * v.y;
                    acc[x][2] += a[x] * v.z;
                    acc[x][3] += a[x] * v.w;
                }
            }

            // depthwise conv + GELU into acc (v read from vt[m][d])
#pragma unroll
            for (int j = 0; j < 4; j++) {
                int d = d0 + j;
                int c = h * DV + d;
                float wv[9];
#pragma unroll
                for (int k2 = 0; k2 < 9; k2++) wv[k2] = g_vlw[c * 9 + k2];
                float vb_ = g_vlb[c];
#pragma unroll
                for (int x = 0; x < 7; x++) {
                    float vl = vb_;
#pragma unroll
                    for (int dy = -1; dy <= 1; dy++) {
                        int yy = y + dy;
                        if (yy < 0 || yy >= 7) continue;
#pragma unroll
                        for (int dx = -1; dx <= 1; dx++) {
                            int xx = x + dx;
                            if (xx < 0 || xx >= 7) continue;
                            vl += wv[(dy + 1) * 3 + (dx + 1)] * r1[(yy * 7 + xx) * VT_STRIDE + d];
                        }
                    }
                    float o = acc[x][j] + vl;
                    acc[x][j] = o * normcdff(o);  // exact GELU
                }
            }

            // store transposed tf32: g_ht[b][n][h*DV + d0 .. +3] via STG.128
            unsigned* hrow = g_ht + ((size_t)b * NN) * DHC + h * DV + d0;
#pragma unroll
            for (int x = 0; x < 7; x++) {
                int n = y * 7 + x;
                uint4 pk;
                pk.x = cvt_tf32(acc[x][0]);
                pk.y = cvt_tf32(acc[x][1]);
                pk.z = cvt_tf32(acc[x][2]);
                pk.w = cvt_tf32(acc[x][3]);
                *(uint4*)&hrow[(size_t)n * DHC] = pk;
            }
        }
    }
}

// ---------------- host ----------------
extern "C" void kernel_launch(void* const* d_in, const int* in_sizes, int n_in,
                              void* d_out, int out_size) {
    const float* x    = (const float*)d_in[0];
    const float* qw   = (const float*)d_in[1];
    const float* qb   = (const float*)d_in[2];
    const float* qs   = (const float*)d_in[3];
    const float* qo   = (const float*)d_in[4];
    const float* kw   = (const float*)d_in[5];
    const float* kb   = (const float*)d_in[6];
    const float* ks   = (const float*)d_in[7];
    const float* ko   = (const float*)d_in[8];
    const float* vw   = (const float*)d_in[9];
    const float* vb   = (const float*)d_in[10];
    const float* vs   = (const float*)d_in[11];
    const float* vo   = (const float*)d_in[12];
    const float* vlw  = (const float*)d_in[13];
    const float* vlb  = (const float*)d_in[14];
    const float* vls  = (const float*)d_in[15];
    const float* vlo  = (const float*)d_in[16];
    const float* th1w = (const float*)d_in[17];
    const float* th1b = (const float*)d_in[18];
    const float* th2w = (const float*)d_in[19];
    const float* th2b = (const float*)d_in[20];
    const float* pw   = (const float*)d_in[21];
    const float* pb   = (const float*)d_in[22];
    const float* ps   = (const float*)d_in[23];
    const float* po   = (const float*)d_in[24];
    const float* ab   = (const float*)d_in[25];

    void *pgw, *pgbias, *pgpw, *pgpb, *pgxt, *pgqkv, *pght;
    cudaGetSymbolAddress(&pgw, g_w);
    cudaGetSymbolAddress(&pgbias, g_bias);
    cudaGetSymbolAddress(&pgpw, g_pw);
    cudaGetSymbolAddress(&pgpb, g_pb);
    cudaGetSymbolAddress(&pgxt, g_xt);
    cudaGetSymbolAddress(&pgqkv, g_qkv);
    cudaGetSymbolAddress(&pght, g_ht);

    cudaFuncSetAttribute(attn_out_kernel, cudaFuncAttributeMaxDynamicSharedMemorySize,
                         SMEM_FLOATS * 4);
    cudaFuncSetAttribute(xt_kernel, cudaFuncAttributeMaxDynamicSharedMemorySize, 75264);

    // 1. fold affines into weights (tf32 + k-permuted)
    prep_kernel<<<(CQKV * DIMC + 255) / 256, 256>>>(qw, qb, qs, qo, kw, kb, ks, ko,
                                                    vw, vb, vs, vo, vlw, vlb, vls, vlo,
                                                    pw, pb, ps, po);
    // 1b. transpose x -> [b][n][c] tf32
    xt_kernel<<<BB, 256, 75264>>>(x);
    // 2. fused QKV projection — tensor cores
    gemm_tc<<<dim3(12, BB), 128>>>((const unsigned*)pgw, (const float*)pgbias,
                                   (const unsigned*)pgxt, (float*)pgqkv, CQKV, DIMC);
    // 3. fused attention core + attn@V + depthwise + GELU -> hidden transposed tf32
    attn_out_kernel<<<BB, 256, SMEM_FLOATS * 4>>>(ab, th1w, th1b, th2w, th2b);
    // 4. output projection — tensor cores
    gemm_tc<<<dim3(3, BB), 128>>>((const unsigned*)pgpw, (const float*)pgpb,
                                  (const unsigned*)pght, (float*)d_out, DIMC, DHC);
}

// round 12
// speedup vs baseline: 1.1673x; 1.1673x over previous
#include <cuda_runtime.h>
#include <math.h>

#define BB 1024
#define DIMC 384
#define NN 49
#define HEADS 8
#define KD 32
#define DV 128
#define DHC 1024
#define CQKV 1536

// k-permutation within groups of 8: puts (k, k+4) fragment pairs adjacent for LDS.64.
#define KPERM(k) (((k) & ~7) | (((k) & 3) << 1) | ((((k) >> 2)) & 1))

// ---------------- scratch (static device allocations) ----------------
__device__ unsigned g_w[CQKV * DIMC];           // fused qkv weights, tf32 bits, k-permuted
__device__ float g_bias[CQKV];
__device__ unsigned g_pw[DIMC * DHC];           // fused proj weights, tf32 bits, k-permuted
__device__ float g_pb[DIMC];
__device__ float g_vlw[DHC * 9];                // fused depthwise weights
__device__ float g_vlb[DHC];
__device__ unsigned g_xt[(size_t)BB * NN * DIMC];   // x transposed [b][n][c], tf32 bits
__device__ float g_qkv[(size_t)BB * CQKV * NN];     // 308 MB
__device__ unsigned g_ht[(size_t)BB * NN * DHC];    // hidden transposed [b][n][d], tf32

// ---------------- tf32 mma helpers ----------------
__device__ __forceinline__ unsigned cvt_tf32(float f) {
    unsigned r;
    asm("cvt.rna.tf32.f32 %0, %1;" : "=r"(r) : "f"(f));
    return r;
}
__device__ __forceinline__ void mma8(float* d, unsigned a0, unsigned a1, unsigned a2,
                                     unsigned a3, unsigned b0, unsigned b1) {
    asm("mma.sync.aligned.m16n8k8.row.col.f32.tf32.tf32.f32 "
        "{%0,%1,%2,%3},{%4,%5,%6,%7},{%8,%9},{%0,%1,%2,%3};"
        : "+f"(d[0]), "+f"(d[1]), "+f"(d[2]), "+f"(d[3])
        : "r"(a0), "r"(a1), "r"(a2), "r"(a3), "r"(b0), "r"(b1));
}

// ---------------- prep: fold BN affines / scales into weights ----------------
__global__ void prep_kernel(const float* __restrict__ qw, const float* __restrict__ qb,
                            const float* __restrict__ qs, const float* __restrict__ qo,
                            const float* __restrict__ kw, const float* __restrict__ kb,
                            const float* __restrict__ ks, const float* __restrict__ ko,
                            const float* __restrict__ vw, const float* __restrict__ vb,
                            const float* __restrict__ vs, const float* __restrict__ vo,
                            const float* __restrict__ vlw, const float* __restrict__ vlb,
                            const float* __restrict__ vls, const float* __restrict__ vlo,
                            const float* __restrict__ pw, const float* __restrict__ pb,
                            const float* __restrict__ ps, const float* __restrict__ po) {
    int i = blockIdx.x * blockDim.x + threadIdx.x;
    const float SCALE = 0.17677669529663687f;  // 32^-0.5, folded into q
    if (i < CQKV * DIMC) {
        int o = i / DIMC, c = i - o * DIMC;
        float v;
        if (o < 256)       v = qw[o * DIMC + c] * qs[o] * SCALE;
        else if (o < 512)  { int oo = o - 256; v = kw[oo * DIMC + c] * ks[oo]; }
        else               { int oo = o - 512; v = vw[oo * DIMC + c] * vs[oo]; }
        g_w[o * DIMC + KPERM(c)] = cvt_tf32(v);
    }
    if (i < CQKV) {
        float v;
        if (i < 256)       v = (qb[i] * qs[i] + qo[i]) * SCALE;
        else if (i < 512)  { int oo = i - 256; v = kb[oo] * ks[oo] + ko[oo]; }
        else               { int oo = i - 512; v = vb[oo] * vs[oo] + vo[oo]; }
        g_bias[i] = v;
    }
    if (i < DIMC * DHC) {
        int o = i / DHC, c = i - o * DHC;
        g_pw[o * DHC + KPERM(c)] = cvt_tf32(pw[i] * ps[o]);
    }
    if (i < DIMC)  g_pb[i] = pb[i] * ps[i] + po[i];
    if (i < DHC * 9) { int c = i / 9; g_vlw[i] = vlw[i] * vls[c]; }
    if (i < DHC)   g_vlb[i] = vlb[i] * vls[i] + vlo[i];
}

// ---------------- transpose x: [b][c][n] fp32 -> [b][n][c] tf32 bits ----------------
__global__ __launch_bounds__(256) void xt_kernel(const float* __restrict__ x) {
    extern __shared__ float sx[];  // 384*49 floats
    int b = blockIdx.x;
    int tid = threadIdx.x;
    const float* xb = x + (size_t)b * DIMC * NN;
    for (int i = tid; i < DIMC * NN; i += 256) sx[i] = xb[i];
    __syncthreads();
    unsigned* ob = g_xt + (size_t)b * NN * DIMC;
    for (int i = tid; i < NN * DIMC; i += 256) {
        int n = i / DIMC, c = i - n * DIMC;
        ob[i] = cvt_tf32(sx[c * NN + n]);
    }
}

// ---------------- tensor-core GEMM (unchanged from R10) ----------------
__global__ __launch_bounds__(128) void gemm_tc(const unsigned* __restrict__ W,
                                               const float* __restrict__ bias,
                                               const unsigned* __restrict__ Xt,
                                               float* __restrict__ Y, int O, int K) {
    __shared__ unsigned ws[128][40];   // [o][k-permuted], stride 40
    __shared__ unsigned xs[56][40];    // [n][k natural], rows 49..55 zero
    __shared__ float bs[128];
    int b = blockIdx.y;
    int obase = blockIdx.x * 128;
    const unsigned* Xb = Xt + (size_t)b * NN * K;
    float* Yb = Y + (size_t)b * O * NN;
    int tid = threadIdx.x;
    int warp = tid >> 5, lane = tid & 31;
    int g = lane >> 2, t = lane & 3;
    int m0 = warp * 32;

    float acc[2][7][4];
#pragma unroll
    for (int mt = 0; mt < 2; mt++)
#pragma unroll
        for (int nt = 0; nt < 7; nt++)
#pragma unroll
            for (int x = 0; x < 4; x++) acc[mt][nt][x] = 0.f;

    bs[tid] = bias[obase + tid];
    for (int i = tid; i < 7 * 40; i += 128) xs[49 + i / 40][i % 40] = 0u;

    for (int c0 = 0; c0 < K; c0 += 32) {
        __syncthreads();
        for (int i = tid; i < 1024; i += 128) {
            int o = i >> 3, c4 = (i & 7) << 2;
            *(uint4*)&ws[o][c4] = *(const uint4*)&W[(size_t)(obase + o) * K + c0 + c4];
        }
        for (int i = tid; i < 392; i += 128) {
            int n = i >> 3, c4 = (i & 7) << 2;
            *(uint4*)&xs[n][c4] = *(const uint4*)&Xb[(size_t)n * K + c0 + c4];
        }
        __syncthreads();
#pragma unroll
        for (int kk8 = 0; kk8 < 4; kk8++) {
            int kc = kk8 * 8 + 2 * t;
            int kn = kk8 * 8 + t;
            uint2 p0 = *(const uint2*)&ws[m0 + g][kc];
            uint2 p1 = *(const uint2*)&ws[m0 + 8 + g][kc];
            uint2 p2 = *(const uint2*)&ws[m0 + 16 + g][kc];
            uint2 p3 = *(const uint2*)&ws[m0 + 24 + g][kc];
#pragma unroll
            for (int nt = 0; nt < 7; nt++) {
                unsigned b0 = xs[nt * 8 + g][kn];
                unsigned b1 = xs[nt * 8 + g][kn + 4];
                mma8(acc[0][nt], p0.x, p1.x, p0.y, p1.y, b0, b1);
                mma8(acc[1][nt], p2.x, p3.x, p2.y, p3.y, b0, b1);
            }
        }
    }

#pragma unroll
    for (int mt = 0; mt < 2; mt++) {
        int r0 = m0 + mt * 16 + g;
        float bv0 = bs[r0], bv1 = bs[r0 + 8];
        size_t base0 = (size_t)(obase + r0) * NN;
        size_t base1 = (size_t)(obase + r0 + 8) * NN;
#pragma unroll
        for (int nt = 0; nt < 7; nt++) {
            int col = nt * 8 + 2 * t;
            if (col < NN) {
                Yb[base0 + col] = acc[mt][nt][0] + bv0;
                Yb[base1 + col] = acc[mt][nt][2] + bv1;
            }
            if (col + 1 < NN) {
                Yb[base0 + col + 1] = acc[mt][nt][1] + bv0;
                Yb[base1 + col + 1] = acc[mt][nt][3] + bv1;
            }
        }
    }
}

// ---------------- fused attention core + attn@V + depthwise + GELU ----------------
// R10 access patterns (conflict-light), but 512 threads (16 warps) for latency hiding:
// every 392-item phase is a single pass, and the AV phase stages TWO heads' V at
// once (2 x 6272 floats in the dead q/k region) with 448 active threads.
__global__ __launch_bounds__(512) void attn_out_kernel(const float* __restrict__ ab,
                                                       const float* __restrict__ th1w_g,
                                                       const float* __restrict__ th1b_g,
                                                       const float* __restrict__ th2w_g,
                                                       const float* __restrict__ th2b_g) {
    extern __shared__ float sm[];
    float* r1 = sm;                 // 25088 floats
    float* r2 = sm + 25088;         // 19208 floats
    float* abs_ = sm + 44296;       // 392
    float* t1w = sm + 44688;        // 64
    float* t1b = sm + 44752;        // 8
    float* t2w = sm + 44760;        // 64
    float* t2b = sm + 44824;        // 8
    int b = blockIdx.x;
    int tid = threadIdx.x;
    const float* qkbase = g_qkv + (size_t)b * CQKV * NN;  // channels 0..511 = q,k

    for (int i = tid; i < (512 * NN) / 4; i += 512)
        ((float4*)r1)[i] = ((const float4*)qkbase)[i];
    if (tid < 392) abs_[tid] = ab[tid];
    if (tid < 64) { t1w[tid] = th1w_g[tid]; t2w[tid] = th2w_g[tid]; }
    if (tid < 8)  { t1b[tid] = th1b_g[tid]; t2b[tid] = th2b_g[tid]; }
    __syncthreads();

    // scores: r2[h,n,m] = q·k (scale folded into q) + rel-pos bias
    if (tid < HEADS * NN) {
        int p = tid;
        int h = p / NN, n = p - h * NN;
        float qv[KD];
#pragma unroll
        for (int kd = 0; kd < KD; kd++) qv[kd] = r1[(h * KD + kd) * NN + n];
        int ny = n / 7, nx = n - ny * 7;
        const float* kb_ = r1 + (256 + h * KD) * NN;
        float* srow = r2 + (size_t)h * NN * NN + n * NN;
        const float* abh = abs_ + h * NN;
        for (int m = 0; m < NN; m++) {
            float s = 0.f;
#pragma unroll
            for (int kd = 0; kd < KD; kd++) s += qv[kd] * kb_[kd * NN + m];
            int my = m / 7, mx = m - my * 7;
            int ridx = abs(ny - my) * 7 + abs(nx - mx);
            srow[m] = s + abh[ridx];
        }
    }
    __syncthreads();

    // th1 head mix -> r1 (q/k space reused)
    if (tid < HEADS * NN) {
        int p = tid;
        int i = p / NN, n = p - i * NN;
        float w[8];
#pragma unroll
        for (int j = 0; j < 8; j++) w[j] = t1w[i * 8 + j];
        float bi = t1b[i];
        const float* base = r2 + n * NN;
        float* orow = r1 + (size_t)p * NN;
        for (int m = 0; m < NN; m++) {
            float s = bi;
#pragma unroll
            for (int j = 0; j < 8; j++) s += w[j] * base[j * 2401 + m];
            orow[m] = s;
        }
    }
    __syncthreads();

    // softmax in place (rows of 49)
    if (tid < HEADS * NN) {
        float* row = r1 + (size_t)tid * NN;
        float mx = row[0];
        for (int m = 1; m < NN; m++) mx = fmaxf(mx, row[m]);
        float sum = 0.f;
        for (int m = 0; m < NN; m++) { float e = __expf(row[m] - mx); row[m] = e; sum += e; }
        float inv = 1.f / sum;
        for (int m = 0; m < NN; m++) row[m] *= inv;
    }
    __syncthreads();

    // th2 head mix -> r2 (raw scores dead)
    if (tid < HEADS * NN) {
        int p = tid;
        int i = p / NN, n = p - i * NN;
        float w[8];
#pragma unroll
        for (int j = 0; j < 8; j++) w[j] = t2w[i * 8 + j];
        float bi = t2b[i];
        const float* base = r1 + n * NN;
        float* orow = r2 + (size_t)i * 2401 + n * NN;
        for (int m = 0; m < NN; m++) {
            float s = bi;
#pragma unroll
            for (int j = 0; j < 8; j++) s += w[j] * base[j * 2401 + m];
            orow[m] = s;
        }
    }

    // per-head-pair: attn@V + depthwise conv + GELU (2 heads' V staged in r1)
    int dg = tid / 7, y = tid - dg * 7;   // dg 0..73; active dg<64
    int hh = dg >> 5;                     // 0/1: which head of the pair
    int dgl = dg & 31;
    int d0 = dgl * 4;
    for (int h0 = 0; h0 < HEADS; h0 += 2) {
        __syncthreads();  // prev pair compute done (and th2 done on first iter)
        const float* vp = g_qkv + (size_t)b * CQKV * NN + (size_t)(512 + h0 * DV) * NN;
        for (int i = tid; i < (2 * DV * NN) / 4; i += 512)
            ((float4*)r1)[i] = ((const float4*)vp)[i];   // [hh][d][n]
        __syncthreads();
        if (dg < 64) {
            int h = h0 + hh;
            const float* vbase = r1 + hh * (DV * NN);
            const float* as_ = r2 + (size_t)h * NN * NN;  // [n*49 + m]
            float acc[7][4];
#pragma unroll
            for (int x = 0; x < 7; x++)
#pragma unroll
                for (int j = 0; j < 4; j++) acc[x][j] = 0.f;

            for (int m = 0; m < NN; m++) {
                float a[7];
#pragma unroll
                for (int x = 0; x < 7; x++) a[x] = as_[(y * 7 + x) * NN + m];
#pragma unroll
                for (int j = 0; j < 4; j++) {
                    float v = vbase[(d0 + j) * NN + m];
#pragma unroll
                    for (int x = 0; x < 7; x++) acc[x][j] += a[x] * v;
                }
            }

            // depthwise conv + GELU into acc
#pragma unroll
            for (int j = 0; j < 4; j++) {
                int d = d0 + j;
                int c = h * DV + d;
                float wv[9];
#pragma unroll
                for (int k2 = 0; k2 < 9; k2++) wv[k2] = g_vlw[c * 9 + k2];
                float vb_ = g_vlb[c];
#pragma unroll
                for (int x = 0; x < 7; x++) {
                    float vl = vb_;
#pragma unroll
                    for (int dy = -1; dy <= 1; dy++) {
                        int yy = y + dy;
                        if (yy < 0 || yy >= 7) continue;
#pragma unroll
                        for (int dx = -1; dx <= 1; dx++) {
                            int xx = x + dx;
                            if (xx < 0 || xx >= 7) continue;
                            vl += wv[(dy + 1) * 3 + (dx + 1)] * vbase[d * NN + yy * 7 + xx];
                        }
                    }
                    float o = acc[x][j] + vl;
                    acc[x][j] = o * normcdff(o);  // exact GELU
                }
            }

            // store transposed tf32: g_ht[b][n][h*DV + d0 .. +3] via STG.128
            unsigned* hrow = g_ht + ((size_t)b * NN) * DHC + h * DV + d0;
#pragma unroll
            for (int x = 0; x < 7; x++) {
                int n = y * 7 + x;
                uint4 pk;
                pk.x = cvt_tf32(acc[x][0]);
                pk.y = cvt_tf32(acc[x][1]);
                pk.z = cvt_tf32(acc[x][2]);
                pk.w = cvt_tf32(acc[x][3]);
                *(uint4*)&hrow[(size_t)n * DHC] = pk;
            }
        }
    }
}

// ---------------- host ----------------
extern "C" void kernel_launch(void* const* d_in, const int* in_sizes, int n_in,
                              void* d_out, int out_size) {
    const float* x    = (const float*)d_in[0];
    const float* qw   = (const float*)d_in[1];
    const float* qb   = (const float*)d_in[2];
    const float* qs   = (const float*)d_in[3];
    const float* qo   = (const float*)d_in[4];
    const float* kw   = (const float*)d_in[5];
    const float* kb   = (const float*)d_in[6];
    const float* ks   = (const float*)d_in[7];
    const float* ko   = (const float*)d_in[8];
    const float* vw   = (const float*)d_in[9];
    const float* vb   = (const float*)d_in[10];
    const float* vs   = (const float*)d_in[11];
    const float* vo   = (const float*)d_in[12];
    const float* vlw  = (const float*)d_in[13];
    const float* vlb  = (const float*)d_in[14];
    const float* vls  = (const float*)d_in[15];
    const float* vlo  = (const float*)d_in[16];
    const float* th1w = (const float*)d_in[17];
    const float* th1b = (const float*)d_in[18];
    const float* th2w = (const float*)d_in[19];
    const float* th2b = (const float*)d_in[20];
    const float* pw   = (const float*)d_in[21];
    const float* pb   = (const float*)d_in[22];
    const float* ps   = (const float*)d_in[23];
    const float* po   = (const float*)d_in[24];
    const float* ab   = (const float*)d_in[25];

    void *pgw, *pgbias, *pgpw, *pgpb, *pgxt, *pgqkv, *pght;
    cudaGetSymbolAddress(&pgw, g_w);
    cudaGetSymbolAddress(&pgbias, g_bias);
    cudaGetSymbolAddress(&pgpw, g_pw);
    cudaGetSymbolAddress(&pgpb, g_pb);
    cudaGetSymbolAddress(&pgxt, g_xt);
    cudaGetSymbolAddress(&pgqkv, g_qkv);
    cudaGetSymbolAddress(&pght, g_ht);

    cudaFuncSetAttribute(attn_out_kernel, cudaFuncAttributeMaxDynamicSharedMemorySize, 179328);
    cudaFuncSetAttribute(xt_kernel, cudaFuncAttributeMaxDynamicSharedMemorySize, 75264);

    // 1. fold affines into weights (tf32 + k-permuted)
    prep_kernel<<<(CQKV * DIMC + 255) / 256, 256>>>(qw, qb, qs, qo, kw, kb, ks, ko,
                                                    vw, vb, vs, vo, vlw, vlb, vls, vlo,
                                                    pw, pb, ps, po);
    // 1b. transpose x -> [b][n][c] tf32
    xt_kernel<<<BB, 256, 75264>>>(x);
    // 2. fused QKV projection — tensor cores
    gemm_tc<<<dim3(12, BB), 128>>>((const unsigned*)pgw, (const float*)pgbias,
                                   (const unsigned*)pgxt, (float*)pgqkv, CQKV, DIMC);
    // 3. fused attention core + attn@V + depthwise + GELU -> hidden transposed tf32
    attn_out_kernel<<<BB, 512, 179328>>>(ab, th1w, th1b, th2w, th2b);
    // 4. output projection — tensor cores
    gemm_tc<<<dim3(3, BB), 128>>>((const unsigned*)pgpw, (const float*)pgpb,
                                  (const unsigned*)pght, (float*)d_out, DIMC, DHC);
}

// round 16
// speedup vs baseline: 1.3707x; 1.1742x over previous
#include <cuda_runtime.h>
#include <math.h>

#define BB 1024
#define DIMC 384
#define NN 49
#define HEADS 8
#define KD 32
#define DV 128
#define DHC 1024
#define CQKV 1536

#define KPERM(k) (((k) & ~7) | (((k) & 3) << 1) | ((((k) >> 2)) & 1))

// ---- attn_out smem map (floats) ----
#define OFF_QN  0            // q natural [c][n]  : 12544
#define OFF_KT  12544        // k transposed [h][m][36] : 14112  (ends 26656)
#define OFF_R2  26656        // scores [h][n][52] (20384) then attn [i][m][56] (21952)
#define OFF_ABS 48608        // 392
#define OFF_T1W 49000
#define OFF_T1B 49064
#define OFF_T2W 49072
#define OFF_T2B 49136
#define AO_SMEM_FLOATS 49144 // 196576 bytes
// th1 output lives at offset 0: [i][n][52] (20384, overwrites dead q/k)
// AV: V staged at offset 0: [hh][m][132] (2*6468)

// ---- gemm smem map (words) ----
#define G_WS0 0
#define G_WS1 5120
#define G_XS0 10240
#define G_XS1 12480
#define G_BS  14720
#define G_SMEM_WORDS 14848   // 59392 bytes

// ---------------- scratch ----------------
__device__ unsigned g_w[CQKV * DIMC];
__device__ float g_bias[CQKV];
__device__ unsigned g_pw[DIMC * DHC];
__device__ float g_pb[DIMC];
__device__ float g_vlw[DHC * 9];
__device__ float g_vlb[DHC];
__device__ unsigned g_xt[(size_t)BB * NN * DIMC];
__device__ float g_qkv[(size_t)BB * CQKV * NN];
__device__ unsigned g_ht[(size_t)BB * NN * DHC];

// ---------------- helpers ----------------
__device__ __forceinline__ unsigned cvt_tf32(float f) {
    unsigned r;
    asm("cvt.rna.tf32.f32 %0, %1;" : "=r"(r) : "f"(f));
    return r;
}
__device__ __forceinline__ void mma8(float* d, unsigned a0, unsigned a1, unsigned a2,
                                     unsigned a3, unsigned b0, unsigned b1) {
    asm("mma.sync.aligned.m16n8k8.row.col.f32.tf32.tf32.f32 "
        "{%0,%1,%2,%3},{%4,%5,%6,%7},{%8,%9},{%0,%1,%2,%3};"
        : "+f"(d[0]), "+f"(d[1]), "+f"(d[2]), "+f"(d[3])
        : "r"(a0), "r"(a1), "r"(a2), "r"(a3), "r"(b0), "r"(b1));
}
__device__ __forceinline__ unsigned smaddr(const void* p) {
    unsigned r;
    asm("{.reg .u64 t; cvta.to.shared.u64 t, %1; cvt.u32.u64 %0, t;}" : "=r"(r) : "l"(p));
    return r;
}

// ---------------- prep ----------------
__global__ void prep_kernel(const float* __restrict__ qw, const float* __restrict__ qb,
                            const float* __restrict__ qs, const float* __restrict__ qo,
                            const float* __restrict__ kw, const float* __restrict__ kb,
                            const float* __restrict__ ks, const float* __restrict__ ko,
                            const float* __restrict__ vw, const float* __restrict__ vb,
                            const float* __restrict__ vs, const float* __restrict__ vo,
                            const float* __restrict__ vlw, const float* __restrict__ vlb,
                            const float* __restrict__ vls, const float* __restrict__ vlo,
                            const float* __restrict__ pw, const float* __restrict__ pb,
                            const float* __restrict__ ps, const float* __restrict__ po) {
    int i = blockIdx.x * blockDim.x + threadIdx.x;
    const float SCALE = 0.17677669529663687f;
    if (i < CQKV * DIMC) {
        int o = i / DIMC, c = i - o * DIMC;
        float v;
        if (o < 256)       v = qw[o * DIMC + c] * qs[o] * SCALE;
        else if (o < 512)  { int oo = o - 256; v = kw[oo * DIMC + c] * ks[oo]; }
        else               { int oo = o - 512; v = vw[oo * DIMC + c] * vs[oo]; }
        g_w[o * DIMC + KPERM(c)] = cvt_tf32(v);
    }
    if (i < CQKV) {
        float v;
        if (i < 256)       v = (qb[i] * qs[i] + qo[i]) * SCALE;
        else if (i < 512)  { int oo = i - 256; v = kb[oo] * ks[oo] + ko[oo]; }
        else               { int oo = i - 512; v = vb[oo] * vs[oo] + vo[oo]; }
        g_bias[i] = v;
    }
    if (i < DIMC * DHC) {
        int o = i / DHC, c = i - o * DHC;
        g_pw[o * DHC + KPERM(c)] = cvt_tf32(pw[i] * ps[o]);
    }
    if (i < DIMC)  g_pb[i] = pb[i] * ps[i] + po[i];
    if (i < DHC * 9) { int c = i / 9; g_vlw[i] = vlw[i] * vls[c]; }
    if (i < DHC)   g_vlb[i] = vlb[i] * vls[i] + vlo[i];
}

// ---------------- transpose x ----------------
__global__ __launch_bounds__(256) void xt_kernel(const float* __restrict__ x) {
    extern __shared__ float sx[];
    int b = blockIdx.x;
    int tid = threadIdx.x;
    const float* xb = x + (size_t)b * DIMC * NN;
    for (int i = tid; i < DIMC * NN; i += 256) sx[i] = xb[i];
    __syncthreads();
    unsigned* ob = g_xt + (size_t)b * NN * DIMC;
    for (int i = tid; i < NN * DIMC; i += 256) {
        int n = i / DIMC, c = i - n * DIMC;
        ob[i] = cvt_tf32(sx[c * NN + n]);
    }
}

// ---------------- tensor-core GEMM with 2-stage cp.async pipeline ----------------
__global__ __launch_bounds__(128) void gemm_tc(const unsigned* __restrict__ W,
                                               const float* __restrict__ bias,
                                               const unsigned* __restrict__ Xt,
                                               float* __restrict__ Y, int O, int K) {
    extern __shared__ unsigned gsm[];
    float* bs = (float*)(gsm + G_BS);
    int b = blockIdx.y, obase = blockIdx.x * 128;
    const unsigned* Wb = W + (size_t)obase * K;
    const unsigned* Xb = Xt + (size_t)b * NN * K;
    float* Yb = Y + (size_t)b * O * NN;
    int tid = threadIdx.x, warp = tid >> 5, lane = tid & 31;
    int g = lane >> 2, t = lane & 3, m0 = warp * 32;

    bs[tid] = bias[obase + tid];
    // zero pad rows 49..55 of both X stages
    for (int i = tid; i < 2 * 7 * 40; i += 128) {
        int s = i / 280, r = i % 280;
        gsm[G_XS0 + s * 2240 + (49 + r / 40) * 40 + (r % 40)] = 0u;
    }
    unsigned wsa = smaddr(gsm);
    unsigned xsa = smaddr(gsm + G_XS0);

    float acc[2][7][4];
#pragma unroll
    for (int mt = 0; mt < 2; mt++)
#pragma unroll
        for (int nt = 0; nt < 7; nt++)
#pragma unroll
            for (int x = 0; x < 4; x++) acc[mt][nt][x] = 0.f;

    auto issue = [&](int c0, int s) {
        unsigned wd = wsa + (unsigned)s * (5120 * 4);
        for (int i = tid; i < 1024; i += 128) {
            int o = i >> 3, c4 = (i & 7) << 2;
            asm volatile("cp.async.cg.shared.global [%0], [%1], 16;"
                         :: "r"(wd + (unsigned)(o * 40 + c4) * 4),
                            "l"(Wb + (size_t)o * K + c0 + c4) : "memory");
        }
        unsigned xd = xsa + (unsigned)s * (2240 * 4);
        for (int i = tid; i < 392; i += 128) {
            int n = i >> 3, c4 = (i & 7) << 2;
            asm volatile("cp.async.cg.shared.global [%0], [%1], 16;"
                         :: "r"(xd + (unsigned)(n * 40 + c4) * 4),
                            "l"(Xb + (size_t)n * K + c0 + c4) : "memory");
        }
        asm volatile("cp.async.commit_group;" ::: "memory");
    };

    int nch = K / 32;
    issue(0, 0);
    for (int c = 0; c < nch; c++) {
        if (c + 1 < nch) {
            issue((c + 1) * 32, (c + 1) & 1);
            asm volatile("cp.async.wait_group 1;" ::: "memory");
        } else {
            asm volatile("cp.async.wait_group 0;" ::: "memory");
        }
        __syncthreads();
        const unsigned* wsc = gsm + (c & 1) * 5120;
        const unsigned* xsc = gsm + G_XS0 + (c & 1) * 2240;
#pragma unroll
        for (int kk8 = 0; kk8 < 4; kk8++) {
            int kc = kk8 * 8 + 2 * t;
            int kn = kk8 * 8 + t;
            uint2 p0 = *(const uint2*)&wsc[(m0 + g) * 40 + kc];
            uint2 p1 = *(const uint2*)&wsc[(m0 + 8 + g) * 40 + kc];
            uint2 p2 = *(const uint2*)&wsc[(m0 + 16 + g) * 40 + kc];
            uint2 p3 = *(const uint2*)&wsc[(m0 + 24 + g) * 40 + kc];
#pragma unroll
            for (int nt = 0; nt < 7; nt++) {
                unsigned b0 = xsc[(nt * 8 + g) * 40 + kn];
                unsigned b1 = xsc[(nt * 8 + g) * 40 + kn + 4];
                mma8(acc[0][nt], p0.x, p1.x, p0.y, p1.y, b0, b1);
                mma8(acc[1][nt], p2.x, p3.x, p2.y, p3.y, b0, b1);
            }
        }
        __syncthreads();
    }

#pragma unroll
    for (int mt = 0; mt < 2; mt++) {
        int r0 = m0 + mt * 16 + g;
        float bv0 = bs[r0], bv1 = bs[r0 + 8];
        size_t base0 = (size_t)(obase + r0) * NN;
        size_t base1 = (size_t)(obase + r0 + 8) * NN;
#pragma unroll
        for (int nt = 0; nt < 7; nt++) {
            int col = nt * 8 + 2 * t;
            if (col < NN) {
                Yb[base0 + col] = acc[mt][nt][0] + bv0;
                Yb[base1 + col] = acc[mt][nt][2] + bv1;
            }
            if (col + 1 < NN) {
                Yb[base0 + col + 1] = acc[mt][nt][1] + bv0;
                Yb[base1 + col + 1] = acc[mt][nt][3] + bv1;
            }
        }
    }
}

// ---------------- fused attention core + attn@V + depthwise + GELU ----------------
__global__ __launch_bounds__(512) void attn_out_kernel(const float* __restrict__ ab,
                                                       const float* __restrict__ th1w_g,
                                                       const float* __restrict__ th1b_g,
                                                       const float* __restrict__ th2w_g,
                                                       const float* __restrict__ th2b_g) {
    extern __shared__ float sm[];
    int b = blockIdx.x;
    int tid = threadIdx.x;
    const float* qkbase = g_qkv + (size_t)b * CQKV * NN;

    // fill: q natural (float4 copy), k transposed [h][m][36]
    for (int i = tid; i < 12544 / 4; i += 512)
        ((float4*)sm)[i] = ((const float4*)qkbase)[i];
    const float* kg = qkbase + 12544;
    for (int i = tid; i < 12544; i += 512) {
        int c = i / NN, n = i - c * NN;
        int h = c >> 5, kd = c & 31;
        sm[OFF_KT + (h * NN + n) * 36 + kd] = kg[i];
    }
    if (tid < 392) sm[OFF_ABS + tid] = ab[tid];
    if (tid < 64) { sm[OFF_T1W + tid] = th1w_g[tid]; sm[OFF_T2W + tid] = th2w_g[tid]; }
    if (tid < 8)  { sm[OFF_T1B + tid] = th1b_g[tid]; sm[OFF_T2B + tid] = th2b_g[tid]; }
    __syncthreads();

    // scores -> r2 [h][n][52]
    if (tid < HEADS * NN) {
        int h = tid / NN, n = tid - h * NN;
        float qv[KD];
#pragma unroll
        for (int kd = 0; kd < KD; kd++) qv[kd] = sm[OFF_QN + (h * KD + kd) * NN + n];
        int ny = n / 7, nx = n - ny * 7;
        const float4* kbase = (const float4*)&sm[OFF_KT + h * NN * 36];
        float* srow = &sm[OFF_R2 + h * 2548 + n * 52];
        const float* abh = &sm[OFF_ABS + h * NN];
        for (int m0 = 0; m0 < 48; m0 += 4) {
            float s4[4];
#pragma unroll
            for (int mi = 0; mi < 4; mi++) {
                int m = m0 + mi;
                const float4* krow = kbase + m * 9;
                float s = 0.f;
#pragma unroll
                for (int q4 = 0; q4 < 8; q4++) {
                    float4 kv = krow[q4];
                    s += qv[4 * q4] * kv.x; s += qv[4 * q4 + 1] * kv.y;
                    s += qv[4 * q4 + 2] * kv.z; s += qv[4 * q4 + 3] * kv.w;
                }
                int my = m / 7, mx = m - my * 7;
                s4[mi] = s + abh[abs(ny - my) * 7 + abs(nx - mx)];
            }
            *(float4*)&srow[m0] = make_float4(s4[0], s4[1], s4[2], s4[3]);
        }
        {   // tail m = 48
            const float4* krow = kbase + 48 * 9;
            float s = 0.f;
#pragma unroll
            for (int q4 = 0; q4 < 8; q4++) {
                float4 kv = krow[q4];
                s += qv[4 * q4] * kv.x; s += qv[4 * q4 + 1] * kv.y;
                s += qv[4 * q4 + 2] * kv.z; s += qv[4 * q4 + 3] * kv.w;
            }
            srow[48] = s + abh[abs(ny - 6) * 7 + abs(nx - 6)];
        }
    }
    __syncthreads();

    // th1: [h][n][52] scores -> [i][n][52] at offset 0 (q/k dead)
    if (tid < HEADS * NN) {
        int i = tid / NN, n = tid - i * NN;
        float w[8];
#pragma unroll
        for (int j = 0; j < 8; j++) w[j] = sm[OFF_T1W + i * 8 + j];
        float bi = sm[OFF_T1B + i];
        const float* base = sm + OFF_R2 + n * 52;
        float* orow = sm + i * 2548 + n * 52;
        for (int m0 = 0; m0 < 48; m0 += 4) {
            float o0 = bi, o1 = bi, o2 = bi, o3 = bi;
#pragma unroll
            for (int j = 0; j < 8; j++) {
                float4 v = *(const float4*)&base[j * 2548 + m0];
                o0 += w[j] * v.x; o1 += w[j] * v.y; o2 += w[j] * v.z; o3 += w[j] * v.w;
            }
            *(float4*)&orow[m0] = make_float4(o0, o1, o2, o3);
        }
        float s = bi;
#pragma unroll
        for (int j = 0; j < 8; j++) s += w[j] * base[j * 2548 + 48];
        orow[48] = s;
    }
    __syncthreads();

    // softmax in place on [i][n][52] rows
    if (tid < HEADS * NN) {
        float* row = sm + (tid / NN) * 2548 + (tid % NN) * 52;
        float mx = row[0];
        for (int m = 1; m < NN; m++) mx = fmaxf(mx, row[m]);
        float sum = 0.f;
        for (int m = 0; m < NN; m++) { float e = __expf(row[m] - mx); row[m] = e; sum += e; }
        float inv = 1.f / sum;
        for (int m = 0; m < NN; m++) row[m] *= inv;
    }
    __syncthreads();

    // th2: [j][n][52] -> attn transposed+padded [i][m][56] in r2 (scores dead)
    if (tid < HEADS * NN) {
        int i = tid / NN, n = tid - i * NN;
        float w[8];
#pragma unroll
        for (int j = 0; j < 8; j++) w[j] = sm[OFF_T2W + i * 8 + j];
        float bi = sm[OFF_T2B + i];
        const float* base = sm + n * 52;
        int ny = n / 7, nx = n - ny * 7;
        float* out = sm + OFF_R2 + i * 2744 + (ny * 8 + nx);
        for (int m0 = 0; m0 < 48; m0 += 4) {
            float o0 = bi, o1 = bi, o2 = bi, o3 = bi;
#pragma unroll
            for (int j = 0; j < 8; j++) {
                float4 v = *(const float4*)&base[j * 2548 + m0];
                o0 += w[j] * v.x; o1 += w[j] * v.y; o2 += w[j] * v.z; o3 += w[j] * v.w;
            }
            out[m0 * 56] = o0; out[(m0 + 1) * 56] = o1;
            out[(m0 + 2) * 56] = o2; out[(m0 + 3) * 56] = o3;
        }
        float s = bi;
#pragma unroll
        for (int j = 0; j < 8; j++) s += w[j] * base[j * 2548 + 48];
        out[48 * 56] = s;
    }

    // AV + depthwise + GELU; V staged transposed [hh][m][132] at offset 0
    int dg = tid / 7, y = tid - dg * 7;
    int hh = dg >> 5, dgl = dg & 31, d0 = dgl * 4;
    for (int h0 = 0; h0 < HEADS; h0 += 2) {
        __syncthreads();  // th2 done (first iter) / prev pair compute done
        const float* vp = qkbase + (size_t)(512 + h0 * DV) * NN;
        for (int i = tid; i < 2 * DV * NN; i += 512) {
            int d = i / NN, n = i - d * NN;     // d 0..255 over 2 heads
            sm[(d >> 7) * 6468 + n * 132 + (d & 127)] = vp[i];
        }
        __syncthreads();
        if (dg < 64) {
            int h = h0 + hh;
            const float* vbase = sm + hh * 6468;
            const float* at_ = sm + OFF_R2 + h * 2744;
            float acc[7][4];
#pragma unroll
            for (int x = 0; x < 7; x++)
#pragma unroll
                for (int j = 0; j < 4; j++) acc[x][j] = 0.f;

            for (int m = 0; m < NN; m++) {
                float4 a03 = *(const float4*)&at_[m * 56 + y * 8];
                float4 a47 = *(const float4*)&at_[m * 56 + y * 8 + 4];
                float4 v = *(const float4*)&vbase[m * 132 + d0];
                float a[7] = {a03.x, a03.y, a03.z, a03.w, a47.x, a47.y, a47.z};
#pragma unroll
                for (int x = 0; x < 7; x++) {
                    acc[x][0] += a[x] * v.x;
                    acc[x][1] += a[x] * v.y;
                    acc[x][2] += a[x] * v.z;
                    acc[x][3] += a[x] * v.w;
                }
            }

#pragma unroll
            for (int j = 0; j < 4; j++) {
                int d = d0 + j;
                int c = h * DV + d;
                float wv[9];
#pragma unroll
                for (int k2 = 0; k2 < 9; k2++) wv[k2] = g_vlw[c * 9 + k2];
                float vb_ = g_vlb[c];
#pragma unroll
                for (int x = 0; x < 7; x++) {
                    float vl = vb_;
#pragma unroll
                    for (int dy = -1; dy <= 1; dy++) {
                        int yy = y + dy;
                        if (yy < 0 || yy >= 7) continue;
#pragma unroll
                        for (int dx = -1; dx <= 1; dx++) {
                            int xx = x + dx;
                            if (xx < 0 || xx >= 7) continue;
                            vl += wv[(dy + 1) * 3 + (dx + 1)] * vbase[(yy * 7 + xx) * 132 + d];
                        }
                    }
                    float o = acc[x][j] + vl;
                    acc[x][j] = o * normcdff(o);
                }
            }

            unsigned* hrow = g_ht + ((size_t)b * NN) * DHC + h * DV + d0;
#pragma unroll
            for (int x = 0; x < 7; x++) {
                int n = y * 7 + x;
                uint4 pk;
                pk.x = cvt_tf32(acc[x][0]);
                pk.y = cvt_tf32(acc[x][1]);
                pk.z = cvt_tf32(acc[x][2]);
                pk.w = cvt_tf32(acc[x][3]);
                *(uint4*)&hrow[(size_t)n * DHC] = pk;
            }
        }
    }
}

// ---------------- host ----------------
extern "C" void kernel_launch(void* const* d_in, const int* in_sizes, int n_in,
                              void* d_out, int out_size) {
    const float* x    = (const float*)d_in[0];
    const float* qw   = (const float*)d_in[1];
    const float* qb   = (const float*)d_in[2];
    const float* qs   = (const float*)d_in[3];
    const float* qo   = (const float*)d_in[4];
    const float* kw   = (const float*)d_in[5];
    const float* kb   = (const float*)d_in[6];
    const float* ks   = (const float*)d_in[7];
    const float* ko   = (const float*)d_in[8];
    const float* vw   = (const float*)d_in[9];
    const float* vb   = (const float*)d_in[10];
    const float* vs   = (const float*)d_in[11];
    const float* vo   = (const float*)d_in[12];
    const float* vlw  = (const float*)d_in[13];
    const float* vlb  = (const float*)d_in[14];
    const float* vls  = (const float*)d_in[15];
    const float* vlo  = (const float*)d_in[16];
    const float* th1w = (const float*)d_in[17];
    const float* th1b = (const float*)d_in[18];
    const float* th2w = (const float*)d_in[19];
    const float* th2b = (const float*)d_in[20];
    const float* pw   = (const float*)d_in[21];
    const float* pb   = (const float*)d_in[22];
    const float* ps   = (const float*)d_in[23];
    const float* po   = (const float*)d_in[24];
    const float* ab   = (const float*)d_in[25];

    void *pgw, *pgbias, *pgpw, *pgpb, *pgxt, *pgqkv, *pght;
    cudaGetSymbolAddress(&pgw, g_w);
    cudaGetSymbolAddress(&pgbias, g_bias);
    cudaGetSymbolAddress(&pgpw, g_pw);
    cudaGetSymbolAddress(&pgpb, g_pb);
    cudaGetSymbolAddress(&pgxt, g_xt);
    cudaGetSymbolAddress(&pgqkv, g_qkv);
    cudaGetSymbolAddress(&pght, g_ht);

    cudaFuncSetAttribute(attn_out_kernel, cudaFuncAttributeMaxDynamicSharedMemorySize,
                         AO_SMEM_FLOATS * 4);
    cudaFuncSetAttribute(gemm_tc, cudaFuncAttributeMaxDynamicSharedMemorySize,
                         G_SMEM_WORDS * 4);
    cudaFuncSetAttribute(xt_kernel, cudaFuncAttributeMaxDynamicSharedMemorySize, 75264);

    prep_kernel<<<(CQKV * DIMC + 255) / 256, 256>>>(qw, qb, qs, qo, kw, kb, ks, ko,
                                                    vw, vb, vs, vo, vlw, vlb, vls, vlo,
                                                    pw, pb, ps, po);
    xt_kernel<<<BB, 256, 75264>>>(x);
    gemm_tc<<<dim3(12, BB), 128, G_SMEM_WORDS * 4>>>((const unsigned*)pgw, (const float*)pgbias,
                                                     (const unsigned*)pgxt, (float*)pgqkv,
                                                     CQKV, DIMC);
    attn_out_kernel<<<BB, 512, AO_SMEM_FLOATS * 4>>>(ab, th1w, th1b, th2w, th2b);
    gemm_tc<<<dim3(3, BB), 128, G_SMEM_WORDS * 4>>>((const unsigned*)pgpw, (const float*)pgpb,
                                                    (const unsigned*)pght, (float*)d_out,
                                                    DIMC, DHC);
}

// round 17
// speedup vs baseline: 1.4328x; 1.0453x over previous
#include <cuda_runtime.h>
#include <math.h>

#define BB 1024
#define DIMC 384
#define NN 49
#define HEADS 8
#define KD 32
#define DV 128
#define DHC 1024
#define CQKV 1536

#define KPERM(k) (((k) & ~7) | (((k) & 3) << 1) | ((((k) >> 2)) & 1))

// ---- attn_out smem map (floats) ----
#define AO_Q    0            // q tf32 [h][n][36] : 14112
#define AO_K    14112        // k tf32 [h][m][36] : 14112 (ends 28224)
#define AO_TH1  0            // th1 out [i][n][52] : 20384 (overwrites q/k)
#define AO_SC   28224        // scores [h][n][52] : 20384
#define AO_ATT  28224        // attn tf32 [i][n][60] : 23520 (overwrites scores)
#define AO_V    0            // V tf32 [hh][d][56] : 14336 (overwrites th1)
#define AO_AVO  14336        // AV out [hh][n][132] : 12936 (ends 27272)
#define AO_ABS  51744
#define AO_T1W  52136
#define AO_T1B  52200
#define AO_T2W  52208
#define AO_T2B  52272
#define AO_TOTAL 52736       // 210944 bytes (includes overread guard pad)

// ---- gemm smem map (words) ----
#define G_XS0 10240
#define G_BS  14720
#define G_SMEM_WORDS 14848   // 59392 bytes

// ---------------- scratch ----------------
__device__ unsigned g_w[CQKV * DIMC];
__device__ float g_bias[CQKV];
__device__ unsigned g_pw[DIMC * DHC];
__device__ float g_pb[DIMC];
__device__ float g_vlw[DHC * 9];
__device__ float g_vlb[DHC];
__device__ unsigned g_xt[(size_t)BB * NN * DIMC];
__device__ float g_qkv[(size_t)BB * CQKV * NN];
__device__ unsigned g_ht[(size_t)BB * NN * DHC];

// ---------------- helpers ----------------
__device__ __forceinline__ unsigned cvt_tf32(float f) {
    unsigned r;
    asm("cvt.rna.tf32.f32 %0, %1;" : "=r"(r) : "f"(f));
    return r;
}
__device__ __forceinline__ void mma8(float* d, unsigned a0, unsigned a1, unsigned a2,
                                     unsigned a3, unsigned b0, unsigned b1) {
    asm("mma.sync.aligned.m16n8k8.row.col.f32.tf32.tf32.f32 "
        "{%0,%1,%2,%3},{%4,%5,%6,%7},{%8,%9},{%0,%1,%2,%3};"
        : "+f"(d[0]), "+f"(d[1]), "+f"(d[2]), "+f"(d[3])
        : "r"(a0), "r"(a1), "r"(a2), "r"(a3), "r"(b0), "r"(b1));
}
__device__ __forceinline__ unsigned smaddr(const void* p) {
    unsigned r;
    asm("{.reg .u64 t; cvta.to.shared.u64 t, %1; cvt.u32.u64 %0, t;}" : "=r"(r) : "l"(p));
    return r;
}
// fast exp on the FMA pipe (avoids the 0.5/cyc/SM MUFU floor)
__device__ __forceinline__ float fexpf(float x) {
    x = fmaxf(x, -80.f);
    float t = x * 1.4426950408889634f;
    float fi = floorf(t);
    float f = t - fi;
    float p = 1.3333558146e-3f;
    p = fmaf(p, f, 9.6181291076e-3f);
    p = fmaf(p, f, 5.5504108665e-2f);
    p = fmaf(p, f, 2.4022650696e-1f);
    p = fmaf(p, f, 6.9314718056e-1f);
    p = fmaf(p, f, 1.0f);
    return __int_as_float(__float_as_int(p) + ((int)fi << 23));
}

// ---------------- prep ----------------
__global__ void prep_kernel(const float* __restrict__ qw, const float* __restrict__ qb,
                            const float* __restrict__ qs, const float* __restrict__ qo,
                            const float* __restrict__ kw, const float* __restrict__ kb,
                            const float* __restrict__ ks, const float* __restrict__ ko,
                            const float* __restrict__ vw, const float* __restrict__ vb,
                            const float* __restrict__ vs, const float* __restrict__ vo,
                            const float* __restrict__ vlw, const float* __restrict__ vlb,
                            const float* __restrict__ vls, const float* __restrict__ vlo,
                            const float* __restrict__ pw, const float* __restrict__ pb,
                            const float* __restrict__ ps, const float* __restrict__ po) {
    int i = blockIdx.x * blockDim.x + threadIdx.x;
    const float SCALE = 0.17677669529663687f;
    if (i < CQKV * DIMC) {
        int o = i / DIMC, c = i - o * DIMC;
        float v;
        if (o < 256)       v = qw[o * DIMC + c] * qs[o] * SCALE;
        else if (o < 512)  { int oo = o - 256; v = kw[oo * DIMC + c] * ks[oo]; }
        else               { int oo = o - 512; v = vw[oo * DIMC + c] * vs[oo]; }
        g_w[o * DIMC + KPERM(c)] = cvt_tf32(v);
    }
    if (i < CQKV) {
        float v;
        if (i < 256)       v = (qb[i] * qs[i] + qo[i]) * SCALE;
        else if (i < 512)  { int oo = i - 256; v = kb[oo] * ks[oo] + ko[oo]; }
        else               { int oo = i - 512; v = vb[oo] * vs[oo] + vo[oo]; }
        g_bias[i] = v;
    }
    if (i < DIMC * DHC) {
        int o = i / DHC, c = i - o * DHC;
        g_pw[o * DHC + KPERM(c)] = cvt_tf32(pw[i] * ps[o]);
    }
    if (i < DIMC)  g_pb[i] = pb[i] * ps[i] + po[i];
    if (i < DHC * 9) { int c = i / 9; g_vlw[i] = vlw[i] * vls[c]; }
    if (i < DHC)   g_vlb[i] = vlb[i] * vls[i] + vlo[i];
}

// ---------------- transpose x ----------------
__global__ __launch_bounds__(256) void xt_kernel(const float* __restrict__ x) {
    extern __shared__ float sx[];
    int b = blockIdx.x;
    int tid = threadIdx.x;
    const float* xb = x + (size_t)b * DIMC * NN;
    for (int i = tid; i < DIMC * NN; i += 256) sx[i] = xb[i];
    __syncthreads();
    unsigned* ob = g_xt + (size_t)b * NN * DIMC;
    for (int i = tid; i < NN * DIMC; i += 256) {
        int n = i / DIMC, c = i - n * DIMC;
        ob[i] = cvt_tf32(sx[c * NN + n]);
    }
}

// ---------------- tensor-core GEMM with 2-stage cp.async pipeline ----------------
__global__ __launch_bounds__(128) void gemm_tc(const unsigned* __restrict__ W,
                                               const float* __restrict__ bias,
                                               const unsigned* __restrict__ Xt,
                                               float* __restrict__ Y, int O, int K) {
    extern __shared__ unsigned gsm[];
    float* bs = (float*)(gsm + G_BS);
    int b = blockIdx.y, obase = blockIdx.x * 128;
    const unsigned* Wb = W + (size_t)obase * K;
    const unsigned* Xb = Xt + (size_t)b * NN * K;
    float* Yb = Y + (size_t)b * O * NN;
    int tid = threadIdx.x, warp = tid >> 5, lane = tid & 31;
    int g = lane >> 2, t = lane & 3, m0 = warp * 32;

    bs[tid] = bias[obase + tid];
    for (int i = tid; i < 2 * 7 * 40; i += 128) {
        int s = i / 280, r = i % 280;
        gsm[G_XS0 + s * 2240 + (49 + r / 40) * 40 + (r % 40)] = 0u;
    }
    unsigned wsa = smaddr(gsm);
    unsigned xsa = smaddr(gsm + G_XS0);

    float acc[2][7][4];
#pragma unroll
    for (int mt = 0; mt < 2; mt++)
#pragma unroll
        for (int nt = 0; nt < 7; nt++)
#pragma unroll
            for (int x = 0; x < 4; x++) acc[mt][nt][x] = 0.f;

    auto issue = [&](int c0, int s) {
        unsigned wd = wsa + (unsigned)s * (5120 * 4);
        for (int i = tid; i < 1024; i += 128) {
            int o = i >> 3, c4 = (i & 7) << 2;
            asm volatile("cp.async.cg.shared.global [%0], [%1], 16;"
                         :: "r"(wd + (unsigned)(o * 40 + c4) * 4),
                            "l"(Wb + (size_t)o * K + c0 + c4) : "memory");
        }
        unsigned xd = xsa + (unsigned)s * (2240 * 4);
        for (int i = tid; i < 392; i += 128) {
            int n = i >> 3, c4 = (i & 7) << 2;
            asm volatile("cp.async.cg.shared.global [%0], [%1], 16;"
                         :: "r"(xd + (unsigned)(n * 40 + c4) * 4),
                            "l"(Xb + (size_t)n * K + c0 + c4) : "memory");
        }
        asm volatile("cp.async.commit_group;" ::: "memory");
    };

    int nch = K / 32;
    issue(0, 0);
    for (int c = 0; c < nch; c++) {
        if (c + 1 < nch) {
            issue((c + 1) * 32, (c + 1) & 1);
            asm volatile("cp.async.wait_group 1;" ::: "memory");
        } else {
            asm volatile("cp.async.wait_group 0;" ::: "memory");
        }
        __syncthreads();
        const unsigned* wsc = gsm + (c & 1) * 5120;
        const unsigned* xsc = gsm + G_XS0 + (c & 1) * 2240;
#pragma unroll
        for (int kk8 = 0; kk8 < 4; kk8++) {
            int kc = kk8 * 8 + 2 * t;
            int kn = kk8 * 8 + t;
            uint2 p0 = *(const uint2*)&wsc[(m0 + g) * 40 + kc];
            uint2 p1 = *(const uint2*)&wsc[(m0 + 8 + g) * 40 + kc];
            uint2 p2 = *(const uint2*)&wsc[(m0 + 16 + g) * 40 + kc];
            uint2 p3 = *(const uint2*)&wsc[(m0 + 24 + g) * 40 + kc];
#pragma unroll
            for (int nt = 0; nt < 7; nt++) {
                unsigned b0 = xsc[(nt * 8 + g) * 40 + kn];
                unsigned b1 = xsc[(nt * 8 + g) * 40 + kn + 4];
                mma8(acc[0][nt], p0.x, p1.x, p0.y, p1.y, b0, b1);
                mma8(acc[1][nt], p2.x, p3.x, p2.y, p3.y, b0, b1);
            }
        }
        __syncthreads();
    }

#pragma unroll
    for (int mt = 0; mt < 2; mt++) {
        int r0 = m0 + mt * 16 + g;
        float bv0 = bs[r0], bv1 = bs[r0 + 8];
        size_t base0 = (size_t)(obase + r0) * NN;
        size_t base1 = (size_t)(obase + r0 + 8) * NN;
#pragma unroll
        for (int nt = 0; nt < 7; nt++) {
            int col = nt * 8 + 2 * t;
            if (col < NN) {
                Yb[base0 + col] = acc[mt][nt][0] + bv0;
                Yb[base1 + col] = acc[mt][nt][2] + bv1;
            }
            if (col + 1 < NN) {
                Yb[base0 + col + 1] = acc[mt][nt][1] + bv0;
                Yb[base1 + col + 1] = acc[mt][nt][3] + bv1;
            }
        }
    }
}

// ---------------- fused attention core (mma) + attn@V (mma) + depthwise + GELU ----
__global__ __launch_bounds__(512) void attn_out_kernel(const float* __restrict__ ab,
                                                       const float* __restrict__ th1w_g,
                                                       const float* __restrict__ th1b_g,
                                                       const float* __restrict__ th2w_g,
                                                       const float* __restrict__ th2b_g) {
    extern __shared__ float sm[];
    int b = blockIdx.x;
    int tid = threadIdx.x;
    int w = tid >> 5, lane = tid & 31, g = lane >> 2, t = lane & 3;
    const float* qkbase = g_qkv + (size_t)b * CQKV * NN;

    // fill: q,k transposed tf32 [h][seq][36]
    for (int i = tid; i < 512 * NN; i += 512) {
        int c = i / NN, n = i - c * NN;
        float v = qkbase[i];
        int base = (c < 256) ? AO_Q : AO_K;
        int sub = c & 255, h = sub >> 5, kd = sub & 31;
        sm[base + (h * NN + n) * 36 + kd] = __uint_as_float(cvt_tf32(v));
    }
    if (tid < 392) sm[AO_ABS + tid] = ab[tid];
    if (tid < 64) { sm[AO_T1W + tid] = th1w_g[tid]; sm[AO_T2W + tid] = th2w_g[tid]; }
    if (tid < 8)  { sm[AO_T1B + tid] = th1b_g[tid]; sm[AO_T2B + tid] = th2b_g[tid]; }
    __syncthreads();

    // ---- scores via mma: warp = (head, row-half); out [h][n][52] + bias ----
    {
        int h = w >> 1, half = w & 1;
        const unsigned* qh = (const unsigned*)(sm + AO_Q + h * (NN * 36));
        const unsigned* kh = (const unsigned*)(sm + AO_K + h * (NN * 36));
        float acc[2][7][4];
#pragma unroll
        for (int j = 0; j < 2; j++)
#pragma unroll
            for (int nt = 0; nt < 7; nt++)
#pragma unroll
                for (int x = 0; x < 4; x++) acc[j][nt][x] = 0.f;
#pragma unroll
        for (int kk = 0; kk < 32; kk += 8) {
            unsigned a[2][4];
#pragma unroll
            for (int j = 0; j < 2; j++) {
                int r = half * 32 + j * 16;
                a[j][0] = qh[(r + g) * 36 + kk + t];
                a[j][1] = qh[(r + 8 + g) * 36 + kk + t];
                a[j][2] = qh[(r + g) * 36 + kk + t + 4];
                a[j][3] = qh[(r + 8 + g) * 36 + kk + t + 4];
            }
#pragma unroll
            for (int nt = 0; nt < 7; nt++) {
                unsigned b0 = kh[(nt * 8 + g) * 36 + kk + t];
                unsigned b1 = kh[(nt * 8 + g) * 36 + kk + t + 4];
                mma8(acc[0][nt], a[0][0], a[0][1], a[0][2], a[0][3], b0, b1);
                mma8(acc[1][nt], a[1][0], a[1][1], a[1][2], a[1][3], b0, b1);
            }
        }
        const float* abh = sm + AO_ABS + h * NN;
        float* sc = sm + AO_SC + h * 2548;
#pragma unroll
        for (int j = 0; j < 2; j++) {
            int rb = half * 32 + j * 16 + g;
#pragma unroll
            for (int nt = 0; nt < 7; nt++) {
                int c0 = nt * 8 + 2 * t;
#pragma unroll
                for (int e = 0; e < 4; e++) {
                    int r = rb + (e >> 1) * 8;
                    int c = c0 + (e & 1);
                    if (r < NN && c < NN) {
                        int ny = r / 7, nx = r - ny * 7;
                        int my = c / 7, mx = c - my * 7;
                        sc[r * 52 + c] = acc[j][nt][e] + abh[abs(ny - my) * 7 + abs(nx - mx)];
                    }
                }
            }
        }
    }
    __syncthreads();

    // ---- th1: scores [h][n][52] -> th1out [i][n][52] at offset 0 ----
    if (tid < HEADS * NN) {
        int i = tid / NN, n = tid - i * NN;
        float ww[8];
#pragma unroll
        for (int j = 0; j < 8; j++) ww[j] = sm[AO_T1W + i * 8 + j];
        float bi = sm[AO_T1B + i];
        const float* base = sm + AO_SC + n * 52;
        float* orow = sm + AO_TH1 + i * 2548 + n * 52;
        for (int m0 = 0; m0 < 48; m0 += 4) {
            float o0 = bi, o1 = bi, o2 = bi, o3 = bi;
#pragma unroll
            for (int j = 0; j < 8; j++) {
                float4 v = *(const float4*)&base[j * 2548 + m0];
                o0 += ww[j] * v.x; o1 += ww[j] * v.y; o2 += ww[j] * v.z; o3 += ww[j] * v.w;
            }
            *(float4*)&orow[m0] = make_float4(o0, o1, o2, o3);
        }
        float s = bi;
#pragma unroll
        for (int j = 0; j < 8; j++) s += ww[j] * base[j * 2548 + 48];
        orow[48] = s;
    }
    __syncthreads();

    // ---- softmax in place (poly exp on FMA pipe) ----
    if (tid < HEADS * NN) {
        float* row = sm + AO_TH1 + (tid / NN) * 2548 + (tid % NN) * 52;
        float mx = row[0];
        for (int m = 1; m < NN; m++) mx = fmaxf(mx, row[m]);
        float sum = 0.f;
        for (int m = 0; m < NN; m++) { float e = fexpf(row[m] - mx); row[m] = e; sum += e; }
        float inv = 1.f / sum;
        for (int m = 0; m < NN; m++) row[m] *= inv;
    }
    __syncthreads();

    // ---- th2: th1out -> attn tf32 [i][n][60], cols 49..55 zeroed ----
    if (tid < HEADS * NN) {
        int i = tid / NN, n = tid - i * NN;
        float ww[8];
#pragma unroll
        for (int j = 0; j < 8; j++) ww[j] = sm[AO_T2W + i * 8 + j];
        float bi = sm[AO_T2B + i];
        const float* base = sm + AO_TH1 + n * 52;
        float* out = sm + AO_ATT + i * 2940 + n * 60;
        for (int m0 = 0; m0 < 48; m0 += 4) {
            float o0 = bi, o1 = bi, o2 = bi, o3 = bi;
#pragma unroll
            for (int j = 0; j < 8; j++) {
                float4 v = *(const float4*)&base[j * 2548 + m0];
                o0 += ww[j] * v.x; o1 += ww[j] * v.y; o2 += ww[j] * v.z; o3 += ww[j] * v.w;
            }
            uint4 pk;
            pk.x = cvt_tf32(o0); pk.y = cvt_tf32(o1); pk.z = cvt_tf32(o2); pk.w = cvt_tf32(o3);
            *(uint4*)&out[m0] = pk;
        }
        float s = bi;
#pragma unroll
        for (int j = 0; j < 8; j++) s += ww[j] * base[j * 2548 + 48];
        out[48] = __uint_as_float(cvt_tf32(s));
#pragma unroll
        for (int m = 49; m < 56; m++) out[m] = 0.f;
    }

    // ---- per head-pair: stage V, AV mma, depthwise + GELU ----
    int hh_m = w >> 3;                       // mma role: head of pair
    int wd = w & 7, mt = wd >> 1, dhalf = wd & 1;
    int dg = tid / 7, y = tid - dg * 7;      // depthwise role
    int hh_d = dg >> 5, d0 = (dg & 31) * 4;
    for (int h0 = 0; h0 < HEADS; h0 += 2) {
        __syncthreads();  // attn ready (first iter) / prev depthwise done
        if (h0 == 0) {
            // zero V pad cols once (region dead after th2)
            for (int i = tid; i < 2 * DV * 7; i += 512) {
                int d = i / 7, m = 49 + i - (i / 7) * 7;
                sm[AO_V + (d >> 7) * 7168 + (d & 127) * 56 + m] = 0.f;
            }
            __syncthreads();
        }
        const float* vp = qkbase + (size_t)(512 + h0 * DV) * NN;
        for (int i = tid; i < 2 * DV * NN; i += 512) {
            int d = i / NN, m = i - d * NN;
            sm[AO_V + (d >> 7) * 7168 + (d & 127) * 56 + m] =
                __uint_as_float(cvt_tf32(vp[i]));
        }
        __syncthreads();

        // AV mma: warp = (hh_m, mtile, dhalf); K = 56 (attn cols 49..55 zero)
        {
            const unsigned* A = (const unsigned*)(sm + AO_ATT + (h0 + hh_m) * 2940);
            const unsigned* B = (const unsigned*)(sm + AO_V + hh_m * 7168 + dhalf * 64 * 56);
            int n0 = mt * 16;
            float acc[8][4];
#pragma unroll
            for (int nt = 0; nt < 8; nt++)
#pragma unroll
                for (int x = 0; x < 4; x++) acc[nt][x] = 0.f;
#pragma unroll
            for (int kk = 0; kk < 56; kk += 8) {
                unsigned a0 = A[(n0 + g) * 60 + kk + t];
                unsigned a1 = A[(n0 + 8 + g) * 60 + kk + t];
                unsigned a2 = A[(n0 + g) * 60 + kk + t + 4];
                unsigned a3 = A[(n0 + 8 + g) * 60 + kk + t + 4];
#pragma unroll
                for (int nt = 0; nt < 8; nt++) {
                    unsigned b0 = B[(nt * 8 + g) * 56 + kk + t];
                    unsigned b1 = B[(nt * 8 + g) * 56 + kk + t + 4];
                    mma8(acc[nt], a0, a1, a2, a3, b0, b1);
                }
            }
            float* O = sm + AO_AVO + hh_m * 6468;
            int r0 = n0 + g;
#pragma unroll
            for (int nt = 0; nt < 8; nt++) {
                int c0 = dhalf * 64 + nt * 8 + 2 * t;
                if (r0 < NN) {
                    O[r0 * 132 + c0] = acc[nt][0];
                    O[r0 * 132 + c0 + 1] = acc[nt][1];
                }
                if (r0 + 8 < NN) {
                    O[(r0 + 8) * 132 + c0] = acc[nt][2];
                    O[(r0 + 8) * 132 + c0 + 1] = acc[nt][3];
                }
            }
        }
        __syncthreads();

        // depthwise + GELU + store
        if (dg < 64) {
            int h = h0 + hh_d;
            const float* avo = sm + AO_AVO + hh_d * 6468;
            const float* vst = sm + AO_V + hh_d * 7168;
            float acc[7][4];
#pragma unroll
            for (int x = 0; x < 7; x++) {
                float4 v = *(const float4*)&avo[(y * 7 + x) * 132 + d0];
                acc[x][0] = v.x; acc[x][1] = v.y; acc[x][2] = v.z; acc[x][3] = v.w;
            }
#pragma unroll
            for (int j = 0; j < 4; j++) {
                int d = d0 + j;
                int c = h * DV + d;
                float wv[9];
#pragma unroll
                for (int k2 = 0; k2 < 9; k2++) wv[k2] = g_vlw[c * 9 + k2];
                float vb_ = g_vlb[c];
#pragma unroll
                for (int x = 0; x < 7; x++) {
                    float vl = vb_;
#pragma unroll
                    for (int dy = -1; dy <= 1; dy++) {
                        int yy = y + dy;
                        if (yy < 0 || yy >= 7) continue;
#pragma unroll
                        for (int dx = -1; dx <= 1; dx++) {
                            int xx = x + dx;
                            if (xx < 0 || xx >= 7) continue;
                            vl += wv[(dy + 1) * 3 + (dx + 1)] * vst[d * 56 + yy * 7 + xx];
                        }
                    }
                    float o = acc[x][j] + vl;
                    acc[x][j] = o * normcdff(o);
                }
            }
            unsigned* hrow = g_ht + ((size_t)b * NN) * DHC + h * DV + d0;
#pragma unroll
            for (int x = 0; x < 7; x++) {
                int n = y * 7 + x;
                uint4 pk;
                pk.x = cvt_tf32(acc[x][0]);
                pk.y = cvt_tf32(acc[x][1]);
                pk.z = cvt_tf32(acc[x][2]);
                pk.w = cvt_tf32(acc[x][3]);
                *(uint4*)&hrow[(size_t)n * DHC] = pk;
            }
        }
    }
}

// ---------------- host ----------------
extern "C" void kernel_launch(void* const* d_in, const int* in_sizes, int n_in,
                              void* d_out, int out_size) {
    const float* x    = (const float*)d_in[0];
    const float* qw   = (const float*)d_in[1];
    const float* qb   = (const float*)d_in[2];
    const float* qs   = (const float*)d_in[3];
    const float* qo   = (const float*)d_in[4];
    const float* kw   = (const float*)d_in[5];
    const float* kb   = (const float*)d_in[6];
    const float* ks   = (const float*)d_in[7];
    const float* ko   = (const float*)d_in[8];
    const float* vw   = (const float*)d_in[9];
    const float* vb   = (const float*)d_in[10];
    const float* vs   = (const float*)d_in[11];
    const float* vo   = (const float*)d_in[12];
    const float* vlw  = (const float*)d_in[13];
    const float* vlb  = (const float*)d_in[14];
    const float* vls  = (const float*)d_in[15];
    const float* vlo  = (const float*)d_in[16];
    const float* th1w = (const float*)d_in[17];
    const float* th1b = (const float*)d_in[18];
    const float* th2w = (const float*)d_in[19];
    const float* th2b = (const float*)d_in[20];
    const float* pw   = (const float*)d_in[21];
    const float* pb   = (const float*)d_in[22];
    const float* ps   = (const float*)d_in[23];
    const float* po   = (const float*)d_in[24];
    const float* ab   = (const float*)d_in[25];

    void *pgw, *pgbias, *pgpw, *pgpb, *pgxt, *pgqkv, *pght;
    cudaGetSymbolAddress(&pgw, g_w);
    cudaGetSymbolAddress(&pgbias, g_bias);
    cudaGetSymbolAddress(&pgpw, g_pw);
    cudaGetSymbolAddress(&pgpb, g_pb);
    cudaGetSymbolAddress(&pgxt, g_xt);
    cudaGetSymbolAddress(&pgqkv, g_qkv);
    cudaGetSymbolAddress(&pght, g_ht);

    cudaFuncSetAttribute(attn_out_kernel, cudaFuncAttributeMaxDynamicSharedMemorySize,
                         AO_TOTAL * 4);
    cudaFuncSetAttribute(gemm_tc, cudaFuncAttributeMaxDynamicSharedMemorySize,
                         G_SMEM_WORDS * 4);
    cudaFuncSetAttribute(xt_kernel, cudaFuncAttributeMaxDynamicSharedMemorySize, 75264);

    prep_kernel<<<(CQKV * DIMC + 255) / 256, 256>>>(qw, qb, qs, qo, kw, kb, ks, ko,
                                                    vw, vb, vs, vo, vlw, vlb, vls, vlo,
                                                    pw, pb, ps, po);
    xt_kernel<<<BB, 256, 75264>>>(x);
    gemm_tc<<<dim3(12, BB), 128, G_SMEM_WORDS * 4>>>((const unsigned*)pgw, (const float*)pgbias,
                                                     (const unsigned*)pgxt, (float*)pgqkv,
                                                     CQKV, DIMC);
    attn_out_kernel<<<BB, 512, AO_TOTAL * 4>>>(ab, th1w, th1b, th2w, th2b);
    gemm_tc<<<dim3(3, BB), 128, G_SMEM_WORDS * 4>>>((const unsigned*)pgpw, (const float*)pgpb,
                                                    (const unsigned*)pght, (float*)d_out,
                                                    DIMC, DHC);
}